// round 3
// baseline (speedup 1.0000x reference)
#include <cuda_runtime.h>
#include <cuda_bf16.h>

// Problem constants
#define Bc          64
#define MAXT        511
#define TP1         512
#define Sdim        1024
#define Hdim        4096
#define W2LD        32
#define ROWS_TOTAL  (Bc * MAXT)          // 32704

// Tiling
#define BM          128
#define BN          64
#define BK          16
#define NTHREADS    256
#define NTILES      ((ROWS_TOTAL + BM - 1) / BM)   // 256
#define KT          (Sdim / BK)          // 64
#define NT          (Hdim / BN)          // 64

// Packed fp32x2 FMA (Blackwell sm_100+, PTX ISA 8.7): d = a*b + d, lanewise on 64-bit pairs.
#define FMA2(d, a, b) asm("fma.rn.f32x2 %0, %1, %2, %0;" : "+l"(d) : "l"(a), "l"(b))

__global__ void zero_out_kernel(float* out) {
    if (threadIdx.x == 0) out[0] = 0.0f;
}

__global__ __launch_bounds__(NTHREADS, 2)
void traj_fused_kernel(const float* __restrict__ S_in,
                       const int*   __restrict__ actions,
                       const int*   __restrict__ lengths,
                       const float* __restrict__ W1,
                       const float* __restrict__ b1,
                       const float* __restrict__ W2,
                       const float* __restrict__ b2,
                       float*       __restrict__ out)
{
    const int tid = threadIdx.x;
    const int R0  = blockIdx.x * BM;

    // ---- Tile liveness: validity is a prefix per batch segment; skip fully-dead tiles ----
    {
        int blo = R0 / MAXT;
        int bhi = (R0 + BM - 1) / MAXT;
        if (bhi >= Bc) bhi = Bc - 1;
        bool live = false;
        for (int b = blo; b <= bhi; ++b) {
            int seg0 = b * MAXT;
            int tmin = (R0 > seg0) ? (R0 - seg0) : 0;
            if (tmin < lengths[b]) live = true;
        }
        if (!live) return;   // uniform across block (no syncs yet)
    }

    __shared__ __align__(16) float smA[2][BK][BM];        // A transposed: [k][row], 16 KB
    __shared__ __align__(16) float smB[2][BK][2 * BN];    // B duplicated pairs, 16 KB
    __shared__ float logit_sm[BM][4];
    __shared__ float block_sum;

    // Thread tile: 16x16 thread grid; each thread computes rows [r0, r0+8) x cols [c0, c0+4)
    const int trow = tid >> 4;
    const int tcol = tid & 15;
    const int r0   = trow * 8;
    const int c0   = tcol * 4;

    // A loader: idx = tid + 256*i -> row = idx>>2 (0..127), kc = idx&3 (float4 column)
    const int a_kc = tid & 3;
    long a_base[2];
    int  a_srow[2];
#pragma unroll
    for (int i = 0; i < 2; ++i) {
        int idx  = tid + NTHREADS * i;
        int lrow = idx >> 2;
        int grow = R0 + lrow;
        if (grow >= ROWS_TOTAL) grow = ROWS_TOTAL - 1;   // clamp (masked later)
        int bb = grow / MAXT;
        int tt = grow - bb * MAXT;
        a_base[i] = (long)(bb * TP1 + tt) * Sdim + a_kc * 4;
        a_srow[i] = lrow;
    }
    // B loader: bk = tid>>4 (k row 0..15), nc = tid&15 (float4 column 0..15)
    const int b_bk = tid >> 4;
    const int b_nc = tid & 15;
    const float* w1_base = W1 + (long)b_bk * Hdim + b_nc * 4;

    // Per-row partial logits (block-0 only: 4 actions), carried across all N-tiles.
    float p[8][4];
#pragma unroll
    for (int i = 0; i < 8; ++i)
#pragma unroll
        for (int a = 0; a < 4; ++a) p[i][a] = 0.0f;

    for (int nt = 0; nt < NT; ++nt) {
        const int n0 = nt * BN;

        unsigned long long acc[4][4];   // row-pairs x cols, packed f32x2
#pragma unroll
        for (int rp = 0; rp < 4; ++rp)
#pragma unroll
            for (int cj = 0; cj < 4; ++cj) acc[rp][cj] = 0ULL;

        // ---- prologue: k-tile 0 into buf 0 ----
        float4 pa0 = *(const float4*)(S_in + a_base[0]);
        float4 pa1 = *(const float4*)(S_in + a_base[1]);
        float4 pb  = *(const float4*)(w1_base + n0);
        {
#pragma unroll
            for (int j = 0; j < 4; ++j) smA[0][a_kc * 4 + j][a_srow[0]] = ((const float*)&pa0)[j];
#pragma unroll
            for (int j = 0; j < 4; ++j) smA[0][a_kc * 4 + j][a_srow[1]] = ((const float*)&pa1)[j];
            float4 d0 = make_float4(pb.x, pb.x, pb.y, pb.y);
            float4 d1 = make_float4(pb.z, pb.z, pb.w, pb.w);
            *(float4*)&smB[0][b_bk][b_nc * 8]     = d0;
            *(float4*)&smB[0][b_bk][b_nc * 8 + 4] = d1;
        }
        __syncthreads();

        int buf = 0;
        for (int kt = 0; kt < KT; ++kt) {
            // prefetch next k-tile into registers (latency hidden by compute)
            if (kt + 1 < KT) {
                const long k0n = (long)(kt + 1) * BK;
                pa0 = *(const float4*)(S_in + a_base[0] + k0n);
                pa1 = *(const float4*)(S_in + a_base[1] + k0n);
                pb  = *(const float4*)(w1_base + k0n * Hdim + n0);
            }
            // compute on current buffer
#pragma unroll
            for (int k = 0; k < BK; ++k) {
                ulonglong2 aA = *(const ulonglong2*)&smA[buf][k][r0];       // rows r0..r0+3
                ulonglong2 aB = *(const ulonglong2*)&smA[buf][k][r0 + 4];   // rows r0+4..r0+7
                ulonglong2 bA = *(const ulonglong2*)&smB[buf][k][c0 * 2];       // cols c0,c0+1 (dup-packed)
                ulonglong2 bB = *(const ulonglong2*)&smB[buf][k][c0 * 2 + 4];   // cols c0+2,c0+3
                FMA2(acc[0][0], aA.x, bA.x); FMA2(acc[0][1], aA.x, bA.y);
                FMA2(acc[0][2], aA.x, bB.x); FMA2(acc[0][3], aA.x, bB.y);
                FMA2(acc[1][0], aA.y, bA.x); FMA2(acc[1][1], aA.y, bA.y);
                FMA2(acc[1][2], aA.y, bB.x); FMA2(acc[1][3], aA.y, bB.y);
                FMA2(acc[2][0], aB.x, bA.x); FMA2(acc[2][1], aB.x, bA.y);
                FMA2(acc[2][2], aB.x, bB.x); FMA2(acc[2][3], aB.x, bB.y);
                FMA2(acc[3][0], aB.y, bA.x); FMA2(acc[3][1], aB.y, bA.y);
                FMA2(acc[3][2], aB.y, bB.x); FMA2(acc[3][3], aB.y, bB.y);
            }
            // store prefetched tile into the other buffer, single barrier per k-tile
            if (kt + 1 < KT) {
                int nb = buf ^ 1;
#pragma unroll
                for (int j = 0; j < 4; ++j) smA[nb][a_kc * 4 + j][a_srow[0]] = ((const float*)&pa0)[j];
#pragma unroll
                for (int j = 0; j < 4; ++j) smA[nb][a_kc * 4 + j][a_srow[1]] = ((const float*)&pa1)[j];
                float4 d0 = make_float4(pb.x, pb.x, pb.y, pb.y);
                float4 d1 = make_float4(pb.z, pb.z, pb.w, pb.w);
                *(float4*)&smB[nb][b_bk][b_nc * 8]     = d0;
                *(float4*)&smB[nb][b_bk][b_nc * 8 + 4] = d1;
            }
            __syncthreads();
            buf ^= 1;
        }

        // ---- fused epilogue: h = relu(acc + b1), partial logits += h * W2[:, 0:4] ----
#pragma unroll
        for (int cj = 0; cj < 4; ++cj) {
            const int col = n0 + c0 + cj;
            const float bias = __ldg(b1 + col);
            const float w0 = __ldg(W2 + (long)col * W2LD + 0);
            const float w1v = __ldg(W2 + (long)col * W2LD + 1);
            const float w2v = __ldg(W2 + (long)col * W2LD + 2);
            const float w3v = __ldg(W2 + (long)col * W2LD + 3);
#pragma unroll
            for (int rp = 0; rp < 4; ++rp) {
                float lo = __uint_as_float((unsigned)(acc[rp][cj] & 0xffffffffULL));
                float hi = __uint_as_float((unsigned)(acc[rp][cj] >> 32));
                float vlo = fmaxf(lo + bias, 0.0f);
                float vhi = fmaxf(hi + bias, 0.0f);
                p[2 * rp    ][0] += vlo * w0;  p[2 * rp    ][1] += vlo * w1v;
                p[2 * rp    ][2] += vlo * w2v; p[2 * rp    ][3] += vlo * w3v;
                p[2 * rp + 1][0] += vhi * w0;  p[2 * rp + 1][1] += vhi * w1v;
                p[2 * rp + 1][2] += vhi * w2v; p[2 * rp + 1][3] += vhi * w3v;
            }
        }
    }

    // ---- reduce partial logits across thread columns ----
    for (int i = tid; i < BM * 4; i += NTHREADS) (&logit_sm[0][0])[i] = 0.0f;
    if (tid == 0) block_sum = 0.0f;
    __syncthreads();
#pragma unroll
    for (int ri = 0; ri < 8; ++ri)
#pragma unroll
        for (int a = 0; a < 4; ++a)
            atomicAdd(&logit_sm[r0 + ri][a], p[ri][a]);
    __syncthreads();

    // ---- per-row log_softmax + gather + mask ----
    if (tid < BM) {
        int grow = R0 + tid;
        if (grow < ROWS_TOTAL) {
            int bb = grow / MAXT;
            int tt = grow - bb * MAXT;
            if (tt < lengths[bb]) {
                float l0 = logit_sm[tid][0] + b2[0];
                float l1 = logit_sm[tid][1] + b2[1];
                float l2 = logit_sm[tid][2] + b2[2];
                float l3 = logit_sm[tid][3] + b2[3];
                float m  = fmaxf(fmaxf(l0, l1), fmaxf(l2, l3));
                float lse = m + logf(expf(l0 - m) + expf(l1 - m) + expf(l2 - m) + expf(l3 - m));
                int act = actions[bb * MAXT + tt];
                float la = (act == 0) ? l0 : (act == 1) ? l1 : (act == 2) ? l2 : l3;
                atomicAdd(&block_sum, la - lse);
            }
        }
    }
    __syncthreads();
    if (tid == 0) atomicAdd(out, -block_sum);
}

extern "C" void kernel_launch(void* const* d_in, const int* in_sizes, int n_in,
                              void* d_out, int out_size) {
    const float* s       = (const float*)d_in[0];
    const int*   actions = (const int*)  d_in[1];
    const int*   lengths = (const int*)  d_in[2];
    const float* W1      = (const float*)d_in[3];
    const float* b1      = (const float*)d_in[4];
    const float* W2      = (const float*)d_in[5];
    const float* b2      = (const float*)d_in[6];
    float* out = (float*)d_out;

    zero_out_kernel<<<1, 32>>>(out);
    traj_fused_kernel<<<NTILES, NTHREADS>>>(s, actions, lengths, W1, b1, W2, b2, out);
}

// round 6
// speedup vs baseline: 12.7283x; 12.7283x over previous
#include <cuda_runtime.h>
#include <cuda_bf16.h>
#include <stdint.h>

// ---------------- Problem constants ----------------
#define Bc          64
#define MAXT        511
#define TP1         512
#define Sdim        1024
#define Hdim        4096
#define W2LD        32
#define ROWS_TOTAL  (Bc * MAXT)            // 32704

// ---------------- Tiling ----------------
#define BM          128
#define BN          128
#define BK          64                     // bf16: 128B rows (SW128)
#define KT          (Sdim / BK)            // 16
#define NT          (Hdim / BN)            // 32
#define NTHREADS    256
#define NTILES      ((ROWS_TOTAL + BM - 1) / BM)   // 256

// ---------------- SMEM layout (dynamic) ----------------
#define A_BYTES     (BM * BK * 2)          // 16384
#define B_BYTES     (BN * BK * 2)          // 16384
#define OFF_A       0
#define OFF_B       (2 * A_BYTES)          // 32768
#define OFF_LOGIT   (OFF_B + 2 * B_BYTES)  // 65536
#define OFF_BSUM    (OFF_LOGIT + BM * 4 * 4)
#define SMEM_BYTES  (OFF_BSUM + 64 + 1024)

// ---------------- bf16 scratch (device globals: allowed) ----------------
__device__ __nv_bfloat16 g_Sbf[(size_t)Bc * TP1 * Sdim];   // 67 MB
__device__ __nv_bfloat16 g_W1T[(size_t)Hdim * Sdim];       // 8 MB, [n][k]

// ---------------- helpers ----------------
__device__ __forceinline__ uint32_t smem_u32(const void* p) {
    uint32_t a;
    asm("{ .reg .u64 t; cvta.to.shared.u64 t, %1; cvt.u32.u64 %0, t; }" : "=r"(a) : "l"(p));
    return a;
}
__device__ __forceinline__ uint32_t swz(uint32_t bo) { return bo ^ ((bo >> 3) & 0x70); }

__device__ __forceinline__ void ldsm4(uint32_t (&r)[4], uint32_t addr) {
    asm volatile("ldmatrix.sync.aligned.m8n8.x4.shared.b16 {%0,%1,%2,%3}, [%4];"
                 : "=r"(r[0]), "=r"(r[1]), "=r"(r[2]), "=r"(r[3]) : "r"(addr));
}
__device__ __forceinline__ void mma16816(float (&c)[4], const uint32_t (&a)[4],
                                         uint32_t b0, uint32_t b1) {
    asm volatile("mma.sync.aligned.m16n8k16.row.col.f32.bf16.bf16.f32 "
                 "{%0,%1,%2,%3}, {%4,%5,%6,%7}, {%8,%9}, {%0,%1,%2,%3};"
                 : "+f"(c[0]), "+f"(c[1]), "+f"(c[2]), "+f"(c[3])
                 : "r"(a[0]), "r"(a[1]), "r"(a[2]), "r"(a[3]), "r"(b0), "r"(b1));
}

// ---------------- conversion pre-kernels ----------------
__global__ void conv_S_kernel(const float* __restrict__ S) {
    size_t n4 = (size_t)Bc * TP1 * Sdim / 4;
    for (size_t i = blockIdx.x * blockDim.x + threadIdx.x; i < n4; i += (size_t)gridDim.x * blockDim.x) {
        float4 v = ((const float4*)S)[i];
        ushort4 o;
        o.x = __bfloat16_as_ushort(__float2bfloat16(v.x));
        o.y = __bfloat16_as_ushort(__float2bfloat16(v.y));
        o.z = __bfloat16_as_ushort(__float2bfloat16(v.z));
        o.w = __bfloat16_as_ushort(__float2bfloat16(v.w));
        ((ushort4*)g_Sbf)[i] = o;
    }
}
__global__ void conv_W1T_kernel(const float* __restrict__ W1) {
    __shared__ float tile[32][33];
    int n0 = blockIdx.x * 32, k0 = blockIdx.y * 32;
    int x = threadIdx.x, y = threadIdx.y;   // block (32,8)
#pragma unroll
    for (int j = 0; j < 32; j += 8)
        tile[y + j][x] = W1[(size_t)(k0 + y + j) * Hdim + n0 + x];
    __syncthreads();
#pragma unroll
    for (int j = 0; j < 32; j += 8)
        g_W1T[(size_t)(n0 + y + j) * Sdim + k0 + x] = __float2bfloat16(tile[x][y + j]);
}
__global__ void zero_out_kernel(float* out) { if (threadIdx.x == 0) out[0] = 0.0f; }

// ---------------- main fused kernel ----------------
__global__ __launch_bounds__(NTHREADS, 1)
void traj_mma_kernel(const int*   __restrict__ actions,
                     const int*   __restrict__ lengths,
                     const float* __restrict__ b1,
                     const float* __restrict__ W2,
                     const float* __restrict__ b2,
                     float*       __restrict__ out)
{
    const int tid = threadIdx.x;
    const int R0  = blockIdx.x * BM;

    // ---- dead-tile skip (validity is a prefix per batch segment) ----
    {
        int blo = R0 / MAXT;
        int bhi = (R0 + BM - 1) / MAXT;
        if (bhi >= Bc) bhi = Bc - 1;
        bool live = false;
        for (int b = blo; b <= bhi; ++b) {
            int seg0 = b * MAXT;
            int tmin = (R0 > seg0) ? (R0 - seg0) : 0;
            if (tmin < lengths[b]) live = true;
        }
        if (!live) return;
    }

    extern __shared__ char smraw[];
    uint32_t sb0 = smem_u32(smraw);
    uint32_t sb  = (sb0 + 1023u) & ~1023u;
    char* smp    = smraw + (sb - sb0);

    const int wid = tid >> 5, lid = tid & 31;
    const int wm  = (wid & 1) * 64;          // warp m base (0/64)
    const int wn  = (wid >> 1) * 32;         // warp n base (0/32/64/96)

    // ---- loader constants: tile = 128 rows x 8 uint4 units ----
    size_t   a_goff[4];  uint32_t sAoff[4];
    size_t   b_goff[4];  uint32_t sBoff[4];
#pragma unroll
    for (int i = 0; i < 4; ++i) {
        int u   = tid + NTHREADS * i;
        int row = u >> 3;                     // 0..127
        int cu  = u & 7;                      // 16B unit
        int grow = R0 + row; if (grow >= ROWS_TOTAL) grow = ROWS_TOTAL - 1;
        int bb = grow / MAXT, tt = grow - bb * MAXT;
        a_goff[i] = (size_t)(bb * TP1 + tt) * Sdim + cu * 8;
        sAoff[i]  = swz((uint32_t)(row * 128 + cu * 16));
        b_goff[i] = (size_t)row * Sdim + cu * 8;      // + nt*BN*Sdim at use
        sBoff[i]  = sAoff[i];
    }

    // ---- fragment address constants ----
    uint32_t aRow[4], bRow[2];
#pragma unroll
    for (int mi = 0; mi < 4; ++mi)
        aRow[mi] = (uint32_t)((wm + 16 * mi + (lid & 7) + ((lid >> 3) & 1) * 8) * 128);
    const uint32_t aCol = (uint32_t)((lid >> 4) * 16);
#pragma unroll
    for (int s = 0; s < 2; ++s)
        bRow[s] = (uint32_t)((wn + 16 * s + (lid & 7) + ((lid >> 4) & 1) * 8) * 128);
    const uint32_t bCol = (uint32_t)(((lid >> 3) & 1) * 16);

    float p[8][4];
#pragma unroll
    for (int r = 0; r < 8; ++r)
#pragma unroll
        for (int a = 0; a < 4; ++a) p[r][a] = 0.0f;

    for (int nt = 0; nt < NT; ++nt) {
        const size_t ntoff = (size_t)nt * BN * Sdim;

        float acc[4][4][4];
#pragma unroll
        for (int mi = 0; mi < 4; ++mi)
#pragma unroll
            for (int nj = 0; nj < 4; ++nj)
#pragma unroll
                for (int q = 0; q < 4; ++q) acc[mi][nj][q] = 0.0f;

        // prologue: k-tile 0 into buf 0
        uint4 pa[4], pb[4];
#pragma unroll
        for (int i = 0; i < 4; ++i) {
            pa[i] = *(const uint4*)(g_Sbf + a_goff[i]);
            pb[i] = *(const uint4*)(g_W1T + ntoff + b_goff[i]);
        }
#pragma unroll
        for (int i = 0; i < 4; ++i) {
            *(uint4*)(smp + OFF_A + sAoff[i]) = pa[i];
            *(uint4*)(smp + OFF_B + sBoff[i]) = pb[i];
        }
        __syncthreads();

        int buf = 0;
        for (int kc = 0; kc < KT; ++kc) {
            if (kc + 1 < KT) {
                const size_t ko = (size_t)(kc + 1) * BK;
#pragma unroll
                for (int i = 0; i < 4; ++i) {
                    pa[i] = *(const uint4*)(g_Sbf + a_goff[i] + ko);
                    pb[i] = *(const uint4*)(g_W1T + ntoff + b_goff[i] + ko);
                }
            }
            // compute on current buffer
            const uint32_t sA = sb + OFF_A + buf * A_BYTES;
            const uint32_t sB = sb + OFF_B + buf * B_BYTES;
#pragma unroll
            for (int ks = 0; ks < 4; ++ks) {
                uint32_t afr[4][4], bfr[2][4];
#pragma unroll
                for (int mi = 0; mi < 4; ++mi)
                    ldsm4(afr[mi], sA + swz(aRow[mi] + ks * 32 + aCol));
#pragma unroll
                for (int s = 0; s < 2; ++s)
                    ldsm4(bfr[s], sB + swz(bRow[s] + ks * 32 + bCol));
#pragma unroll
                for (int mi = 0; mi < 4; ++mi) {
                    mma16816(acc[mi][0], afr[mi], bfr[0][0], bfr[0][1]);
                    mma16816(acc[mi][1], afr[mi], bfr[0][2], bfr[0][3]);
                    mma16816(acc[mi][2], afr[mi], bfr[1][0], bfr[1][1]);
                    mma16816(acc[mi][3], afr[mi], bfr[1][2], bfr[1][3]);
                }
            }
            if (kc + 1 < KT) {
                const int nb = buf ^ 1;
#pragma unroll
                for (int i = 0; i < 4; ++i) {
                    *(uint4*)(smp + OFF_A + nb * A_BYTES + sAoff[i]) = pa[i];
                    *(uint4*)(smp + OFF_B + nb * B_BYTES + sBoff[i]) = pb[i];
                }
            }
            __syncthreads();
            buf ^= 1;
        }

        // ---- fused epilogue on register fragments ----
        // lane owns: rows wm+16*mi+(lid>>2)+8*rp ; cols nt*BN+wn+8*nj+2*(lid&3)+{0,1}
#pragma unroll
        for (int nj = 0; nj < 4; ++nj) {
            const int cbase = nt * BN + wn + 8 * nj + 2 * (lid & 3);
            const float b1a = __ldg(b1 + cbase);
            const float b1b = __ldg(b1 + cbase + 1);
            float w2a[4], w2b[4];
#pragma unroll
            for (int a = 0; a < 4; ++a) {
                w2a[a] = __ldg(W2 + (size_t)cbase * W2LD + a);
                w2b[a] = __ldg(W2 + (size_t)(cbase + 1) * W2LD + a);
            }
#pragma unroll
            for (int mi = 0; mi < 4; ++mi) {
                float h0 = fmaxf(acc[mi][nj][0] + b1a, 0.0f);
                float h1 = fmaxf(acc[mi][nj][1] + b1b, 0.0f);
                float h2 = fmaxf(acc[mi][nj][2] + b1a, 0.0f);
                float h3 = fmaxf(acc[mi][nj][3] + b1b, 0.0f);
#pragma unroll
                for (int a = 0; a < 4; ++a) {
                    p[2 * mi    ][a] += h0 * w2a[a] + h1 * w2b[a];
                    p[2 * mi + 1][a] += h2 * w2a[a] + h3 * w2b[a];
                }
            }
        }
    }

    // ---- reduce partial logits across lanes/warps ----
    float* logit = (float*)(smp + OFF_LOGIT);
    float* bsum  = (float*)(smp + OFF_BSUM);
    for (int i = tid; i < BM * 4; i += NTHREADS) logit[i] = 0.0f;
    if (tid == 0) *bsum = 0.0f;
    __syncthreads();
#pragma unroll
    for (int pr = 0; pr < 8; ++pr) {
        int row = wm + 16 * (pr >> 1) + (lid >> 2) + 8 * (pr & 1);
#pragma unroll
        for (int a = 0; a < 4; ++a)
            atomicAdd(&logit[row * 4 + a], p[pr][a]);
    }
    __syncthreads();

    // ---- per-row log_softmax + gather + mask ----
    if (tid < BM) {
        int grow = R0 + tid;
        if (grow < ROWS_TOTAL) {
            int bb = grow / MAXT, tt = grow - bb * MAXT;
            if (tt < lengths[bb]) {
                float l0 = logit[tid * 4 + 0] + b2[0];
                float l1 = logit[tid * 4 + 1] + b2[1];
                float l2 = logit[tid * 4 + 2] + b2[2];
                float l3 = logit[tid * 4 + 3] + b2[3];
                float m  = fmaxf(fmaxf(l0, l1), fmaxf(l2, l3));
                float lse = m + logf(expf(l0 - m) + expf(l1 - m) + expf(l2 - m) + expf(l3 - m));
                int act = actions[bb * MAXT + tt];
                float la = (act == 0) ? l0 : (act == 1) ? l1 : (act == 2) ? l2 : l3;
                atomicAdd(bsum, la - lse);
            }
        }
    }
    __syncthreads();
    if (tid == 0) atomicAdd(out, -(*bsum));
}

// ---------------- launch ----------------
extern "C" void kernel_launch(void* const* d_in, const int* in_sizes, int n_in,
                              void* d_out, int out_size) {
    const float* s       = (const float*)d_in[0];
    const int*   actions = (const int*)  d_in[1];
    const int*   lengths = (const int*)  d_in[2];
    const float* W1      = (const float*)d_in[3];
    const float* b1      = (const float*)d_in[4];
    const float* W2      = (const float*)d_in[5];
    const float* b2      = (const float*)d_in[6];
    float* out = (float*)d_out;

    cudaFuncSetAttribute(traj_mma_kernel, cudaFuncAttributeMaxDynamicSharedMemorySize, SMEM_BYTES);

    conv_S_kernel<<<4096, 256>>>(s);
    conv_W1T_kernel<<<dim3(Hdim / 32, Sdim / 32), dim3(32, 8)>>>(W1);
    zero_out_kernel<<<1, 32>>>(out);
    traj_mma_kernel<<<NTILES, NTHREADS, SMEM_BYTES>>>(actions, lengths, b1, W2, b2, out);
}

// round 7
// speedup vs baseline: 15.9028x; 1.2494x over previous
#include <cuda_runtime.h>
#include <cuda_bf16.h>
#include <stdint.h>

// ---------------- Problem constants ----------------
#define Bc          64
#define MAXT        511
#define TP1         512
#define Sdim        1024
#define Hdim        4096
#define W2LD        32
#define ROWS_TOTAL  (Bc * MAXT)            // 32704

// ---------------- Tiling ----------------
#define BM          128
#define BN          128
#define BK          64                     // bf16: 128B rows (SW128)
#define KT          (Sdim / BK)            // 16
#define NT          (Hdim / BN)            // 32
#define NCHUNK      4                      // H-split for load balance
#define NT_PER      (NT / NCHUNK)          // 8
#define NTHREADS    256
#define NTILES      ((ROWS_TOTAL + BM - 1) / BM)   // 256

// ---------------- SMEM layout (dynamic) ----------------
#define A_BYTES     (BM * BK * 2)          // 16384
#define B_BYTES     (BN * BK * 2)          // 16384
#define OFF_A       0
#define OFF_B       (2 * A_BYTES)          // 32768
#define OFF_LOGIT   (OFF_B + 2 * B_BYTES)  // 65536
#define SMEM_BYTES  (OFF_LOGIT + BM * 4 * 4 + 1024)

// ---------------- device-global scratch ----------------
__device__ __nv_bfloat16 g_Sbf[(size_t)Bc * TP1 * Sdim];   // 67 MB
__device__ __nv_bfloat16 g_W1T[(size_t)Hdim * Sdim];       // 8 MB, [n][k]
__device__ float         g_logit[(size_t)ROWS_TOTAL * 4];  // partial logits

// ---------------- helpers ----------------
__device__ __forceinline__ uint32_t smem_u32(const void* p) {
    uint32_t a;
    asm("{ .reg .u64 t; cvta.to.shared.u64 t, %1; cvt.u32.u64 %0, t; }" : "=r"(a) : "l"(p));
    return a;
}
__device__ __forceinline__ uint32_t swz(uint32_t bo) { return bo ^ ((bo >> 3) & 0x70); }

__device__ __forceinline__ void ldsm4(uint32_t (&r)[4], uint32_t addr) {
    asm volatile("ldmatrix.sync.aligned.m8n8.x4.shared.b16 {%0,%1,%2,%3}, [%4];"
                 : "=r"(r[0]), "=r"(r[1]), "=r"(r[2]), "=r"(r[3]) : "r"(addr));
}
__device__ __forceinline__ void mma16816(float (&c)[4], const uint32_t (&a)[4],
                                         uint32_t b0, uint32_t b1) {
    asm volatile("mma.sync.aligned.m16n8k16.row.col.f32.bf16.bf16.f32 "
                 "{%0,%1,%2,%3}, {%4,%5,%6,%7}, {%8,%9}, {%0,%1,%2,%3};"
                 : "+f"(c[0]), "+f"(c[1]), "+f"(c[2]), "+f"(c[3])
                 : "r"(a[0]), "r"(a[1]), "r"(a[2]), "r"(a[3]), "r"(b0), "r"(b1));
}

// ---------------- pre-kernels ----------------
__global__ void conv_S_kernel(const float* __restrict__ S) {
    size_t n4 = (size_t)Bc * TP1 * Sdim / 4;
    for (size_t i = blockIdx.x * blockDim.x + threadIdx.x; i < n4; i += (size_t)gridDim.x * blockDim.x) {
        float4 v = ((const float4*)S)[i];
        ushort4 o;
        o.x = __bfloat16_as_ushort(__float2bfloat16(v.x));
        o.y = __bfloat16_as_ushort(__float2bfloat16(v.y));
        o.z = __bfloat16_as_ushort(__float2bfloat16(v.z));
        o.w = __bfloat16_as_ushort(__float2bfloat16(v.w));
        ((ushort4*)g_Sbf)[i] = o;
    }
}
__global__ void conv_W1T_kernel(const float* __restrict__ W1) {
    __shared__ float tile[32][33];
    int n0 = blockIdx.x * 32, k0 = blockIdx.y * 32;
    int x = threadIdx.x, y = threadIdx.y;   // block (32,8)
#pragma unroll
    for (int j = 0; j < 32; j += 8)
        tile[y + j][x] = W1[(size_t)(k0 + y + j) * Hdim + n0 + x];
    __syncthreads();
#pragma unroll
    for (int j = 0; j < 32; j += 8)
        g_W1T[(size_t)(n0 + y + j) * Sdim + k0 + x] = __float2bfloat16(tile[x][y + j]);
}
__global__ void zero_scratch_kernel(float* out) {
    size_t n = (size_t)ROWS_TOTAL * 4;
    for (size_t i = blockIdx.x * blockDim.x + threadIdx.x; i < n; i += (size_t)gridDim.x * blockDim.x)
        g_logit[i] = 0.0f;
    if (blockIdx.x == 0 && threadIdx.x == 0) out[0] = 0.0f;
}

// ---------------- main fused kernel ----------------
__global__ __launch_bounds__(NTHREADS, 1)
void traj_mma_kernel(const int* __restrict__ lengths,
                     const float* __restrict__ b1,
                     const float* __restrict__ W2)
{
    const int tid   = threadIdx.x;
    const int tile  = blockIdx.x >> 2;
    const int chunk = blockIdx.x & 3;
    const int R0    = tile * BM;

    // ---- dead-tile skip (validity is a prefix per batch segment) ----
    {
        int blo = R0 / MAXT;
        int bhi = (R0 + BM - 1) / MAXT;
        if (bhi >= Bc) bhi = Bc - 1;
        bool live = false;
        for (int b = blo; b <= bhi; ++b) {
            int seg0 = b * MAXT;
            int tmin = (R0 > seg0) ? (R0 - seg0) : 0;
            if (tmin < lengths[b]) live = true;
        }
        if (!live) return;
    }

    extern __shared__ char smraw[];
    uint32_t sb0 = smem_u32(smraw);
    uint32_t sb  = (sb0 + 1023u) & ~1023u;
    char* smp    = smraw + (sb - sb0);

    const int wid = tid >> 5, lid = tid & 31;
    const int wm  = (wid & 1) * 64;          // warp m base (0/64)
    const int wn  = (wid >> 1) * 32;         // warp n base (0/32/64/96)

    // ---- loader constants ----
    size_t   a_goff[4];  uint32_t sAoff[4];
    size_t   b_goff[4];
#pragma unroll
    for (int i = 0; i < 4; ++i) {
        int u   = tid + NTHREADS * i;
        int row = u >> 3;                     // 0..127
        int cu  = u & 7;                      // 16B unit
        int grow = R0 + row; if (grow >= ROWS_TOTAL) grow = ROWS_TOTAL - 1;
        int bb = grow / MAXT, tt = grow - bb * MAXT;
        a_goff[i] = (size_t)(bb * TP1 + tt) * Sdim + cu * 8;
        sAoff[i]  = swz((uint32_t)(row * 128 + cu * 16));
        b_goff[i] = (size_t)row * Sdim + cu * 8;      // + nt*BN*Sdim at use
    }

    // ---- fragment address constants ----
    uint32_t aRow[4], bRow[2];
#pragma unroll
    for (int mi = 0; mi < 4; ++mi)
        aRow[mi] = (uint32_t)((wm + 16 * mi + (lid & 7) + ((lid >> 3) & 1) * 8) * 128);
    const uint32_t aCol = (uint32_t)((lid >> 4) * 16);
#pragma unroll
    for (int s = 0; s < 2; ++s)
        bRow[s] = (uint32_t)((wn + 16 * s + (lid & 7) + ((lid >> 4) & 1) * 8) * 128);
    const uint32_t bCol = (uint32_t)(((lid >> 3) & 1) * 16);

    float p[8][4];
#pragma unroll
    for (int r = 0; r < 8; ++r)
#pragma unroll
        for (int a = 0; a < 4; ++a) p[r][a] = 0.0f;

    for (int nt = chunk * NT_PER; nt < (chunk + 1) * NT_PER; ++nt) {
        const size_t ntoff = (size_t)nt * BN * Sdim;

        float acc[4][4][4];
#pragma unroll
        for (int mi = 0; mi < 4; ++mi)
#pragma unroll
            for (int nj = 0; nj < 4; ++nj)
#pragma unroll
                for (int q = 0; q < 4; ++q) acc[mi][nj][q] = 0.0f;

        // prologue: k-tile 0 into buf 0
        uint4 pa[4], pb[4];
#pragma unroll
        for (int i = 0; i < 4; ++i) {
            pa[i] = *(const uint4*)(g_Sbf + a_goff[i]);
            pb[i] = *(const uint4*)(g_W1T + ntoff + b_goff[i]);
        }
#pragma unroll
        for (int i = 0; i < 4; ++i) {
            *(uint4*)(smp + OFF_A + sAoff[i]) = pa[i];
            *(uint4*)(smp + OFF_B + sAoff[i]) = pb[i];
        }
        __syncthreads();

        int buf = 0;
        for (int kc = 0; kc < KT; ++kc) {
            if (kc + 1 < KT) {
                const size_t ko = (size_t)(kc + 1) * BK;
#pragma unroll
                for (int i = 0; i < 4; ++i) {
                    pa[i] = *(const uint4*)(g_Sbf + a_goff[i] + ko);
                    pb[i] = *(const uint4*)(g_W1T + ntoff + b_goff[i] + ko);
                }
            }
            const uint32_t sA = sb + OFF_A + buf * A_BYTES;
            const uint32_t sB = sb + OFF_B + buf * B_BYTES;
#pragma unroll
            for (int ks = 0; ks < 4; ++ks) {
                uint32_t afr[4][4], bfr[2][4];
#pragma unroll
                for (int mi = 0; mi < 4; ++mi)
                    ldsm4(afr[mi], sA + swz(aRow[mi] + ks * 32 + aCol));
#pragma unroll
                for (int s = 0; s < 2; ++s)
                    ldsm4(bfr[s], sB + swz(bRow[s] + ks * 32 + bCol));
#pragma unroll
                for (int mi = 0; mi < 4; ++mi) {
                    mma16816(acc[mi][0], afr[mi], bfr[0][0], bfr[0][1]);
                    mma16816(acc[mi][1], afr[mi], bfr[0][2], bfr[0][3]);
                    mma16816(acc[mi][2], afr[mi], bfr[1][0], bfr[1][1]);
                    mma16816(acc[mi][3], afr[mi], bfr[1][2], bfr[1][3]);
                }
            }
            if (kc + 1 < KT) {
                const int nb = buf ^ 1;
#pragma unroll
                for (int i = 0; i < 4; ++i) {
                    *(uint4*)(smp + OFF_A + nb * A_BYTES + sAoff[i]) = pa[i];
                    *(uint4*)(smp + OFF_B + nb * B_BYTES + sAoff[i]) = pb[i];
                }
            }
            __syncthreads();
            buf ^= 1;
        }

        // ---- fused epilogue on register fragments ----
#pragma unroll
        for (int nj = 0; nj < 4; ++nj) {
            const int cbase = nt * BN + wn + 8 * nj + 2 * (lid & 3);
            const float b1a = __ldg(b1 + cbase);
            const float b1b = __ldg(b1 + cbase + 1);
            float w2a[4], w2b[4];
#pragma unroll
            for (int a = 0; a < 4; ++a) {
                w2a[a] = __ldg(W2 + (size_t)cbase * W2LD + a);
                w2b[a] = __ldg(W2 + (size_t)(cbase + 1) * W2LD + a);
            }
#pragma unroll
            for (int mi = 0; mi < 4; ++mi) {
                float h0 = fmaxf(acc[mi][nj][0] + b1a, 0.0f);
                float h1 = fmaxf(acc[mi][nj][1] + b1b, 0.0f);
                float h2 = fmaxf(acc[mi][nj][2] + b1a, 0.0f);
                float h3 = fmaxf(acc[mi][nj][3] + b1b, 0.0f);
#pragma unroll
                for (int a = 0; a < 4; ++a) {
                    p[2 * mi    ][a] += h0 * w2a[a] + h1 * w2b[a];
                    p[2 * mi + 1][a] += h2 * w2a[a] + h3 * w2b[a];
                }
            }
        }
    }

    // ---- reduce partial logits in smem, then one global atomic set per row ----
    float* logit = (float*)(smp + OFF_LOGIT);
    for (int i = tid; i < BM * 4; i += NTHREADS) logit[i] = 0.0f;
    __syncthreads();
#pragma unroll
    for (int pr = 0; pr < 8; ++pr) {
        int row = wm + 16 * (pr >> 1) + (lid >> 2) + 8 * (pr & 1);
#pragma unroll
        for (int a = 0; a < 4; ++a)
            atomicAdd(&logit[row * 4 + a], p[pr][a]);
    }
    __syncthreads();
    if (tid < BM) {
        int grow = R0 + tid;
        if (grow < ROWS_TOTAL) {
#pragma unroll
            for (int a = 0; a < 4; ++a)
                atomicAdd(&g_logit[(size_t)grow * 4 + a], logit[tid * 4 + a]);
        }
    }
}

// ---------------- finalize: logsumexp + gather + mask + sum ----------------
__global__ void traj_finalize_kernel(const int* __restrict__ actions,
                                     const int* __restrict__ lengths,
                                     const float* __restrict__ b2,
                                     float* __restrict__ out)
{
    int row = blockIdx.x * 128 + threadIdx.x;
    float local = 0.0f;
    if (row < ROWS_TOTAL) {
        int bb = row / MAXT, tt = row - bb * MAXT;
        if (tt < lengths[bb]) {
            float l0 = g_logit[(size_t)row * 4 + 0] + b2[0];
            float l1 = g_logit[(size_t)row * 4 + 1] + b2[1];
            float l2 = g_logit[(size_t)row * 4 + 2] + b2[2];
            float l3 = g_logit[(size_t)row * 4 + 3] + b2[3];
            float m  = fmaxf(fmaxf(l0, l1), fmaxf(l2, l3));
            float lse = m + logf(expf(l0 - m) + expf(l1 - m) + expf(l2 - m) + expf(l3 - m));
            int act = actions[bb * MAXT + tt];
            float la = (act == 0) ? l0 : (act == 1) ? l1 : (act == 2) ? l2 : l3;
            local = lse - la;                     // contributes +(lse-la) to -total_logp
        }
    }
#pragma unroll
    for (int o = 16; o > 0; o >>= 1)
        local += __shfl_xor_sync(0xFFFFFFFFu, local, o);
    if ((threadIdx.x & 31) == 0 && local != 0.0f) atomicAdd(out, local);
}

// ---------------- launch ----------------
extern "C" void kernel_launch(void* const* d_in, const int* in_sizes, int n_in,
                              void* d_out, int out_size) {
    const float* s       = (const float*)d_in[0];
    const int*   actions = (const int*)  d_in[1];
    const int*   lengths = (const int*)  d_in[2];
    const float* W1      = (const float*)d_in[3];
    const float* b1      = (const float*)d_in[4];
    const float* W2      = (const float*)d_in[5];
    const float* b2      = (const float*)d_in[6];
    float* out = (float*)d_out;

    cudaFuncSetAttribute(traj_mma_kernel, cudaFuncAttributeMaxDynamicSharedMemorySize, SMEM_BYTES);

    conv_S_kernel<<<4096, 256>>>(s);
    conv_W1T_kernel<<<dim3(Hdim / 32, Sdim / 32), dim3(32, 8)>>>(W1);
    zero_scratch_kernel<<<512, 256>>>(out);
    traj_mma_kernel<<<NTILES * NCHUNK, NTHREADS, SMEM_BYTES>>>(lengths, b1, W2);
    traj_finalize_kernel<<<(ROWS_TOTAL + 127) / 128, 128>>>(actions, lengths, b2, out);
}